// round 13
// baseline (speedup 1.0000x reference)
#include <cuda_runtime.h>

// Problem constants
#define B_   16
#define K_   64
#define BK   1024
#define IN_  128
#define H0   192
#define H1   64
#define UNF  6
#define HS   (H0 + H1)        // 256
#define L2E  1.4426950408889634f
#define RMAX 7
#define NCTA 147              // ceil(1024 / 7)
#define NTHR 576              // 3 warpgroups of 192

// -------- device scratch --------
// g_d0[i*H0+h]: (i&3)<2  tanh path: {0.5*sig, -0.5*sig*mu, 0.5*relu(w)*erev, 0.5*relu(w)}
//               (i&3)>=2 ex2  path: {-L2E*sig, +L2E*sig*mu, relu(w)*erev, relu(w)}
__device__ float4 g_d0[H0 * H0];
__device__ float4 g_d1[H1 * H1];
__device__ float4 g_din1[H0 * H1];
__device__ float4 g_hc0[H0];       // {gl*vleak, gl, 1/(relu(cm)+eps), gdiff*sqrt(dt)}
__device__ float4 g_hc1[H1];
__device__ float2 g_sums0[H0];     // PARTIAL column sums {0.5*wz, 0.5*ww}, tanh-path i only
__device__ float2 g_sums1[H1];
__device__ float2 g_sumsin1[H1];
__device__ float  g_A0n[B_ * H0];
__device__ float  g_A0d[B_ * H0];
__device__ float  g_wts[B_ * K_];
__device__ float  g_s1[BK * H1];
__device__ int    g_cnt[B_];

__device__ __forceinline__ float tanhfast(float x) {
    float r; asm("tanh.approx.f32 %0, %1;" : "=f"(r) : "f"(x)); return r;
}
__device__ __forceinline__ float ex2f(float x) {
    float r; asm("ex2.approx.f32 %0, %1;" : "=f"(r) : "f"(x)); return r;
}
__device__ __forceinline__ float rcpf(float x) {
    float r; asm("rcp.approx.f32 %0, %1;" : "=f"(r) : "f"(x)); return r;
}
__device__ __forceinline__ float relu_(float x) { return x > 0.f ? x : 0.f; }
__device__ __forceinline__ float4 ldcg4(const float4* p) {
    float4 v;
    asm volatile("ld.global.cg.v4.f32 {%0,%1,%2,%3}, [%4];"
                 : "=f"(v.x), "=f"(v.y), "=f"(v.z), "=f"(v.w) : "l"(p));
    return v;
}
// FMA-pipe reciprocal of d >= 1 (magic seed + 2 Newton); rel err ~6e-6
__device__ __forceinline__ float rcp_fma(float d) {
    float x = __int_as_float(0x7EF311C3 - __float_as_int(d));
    x = x * fmaf(-d, x, 2.0f);
    x = x * fmaf(-d, x, 2.0f);
    return x;
}

// ================= precompute =================
__global__ void precompute_kernel(
    const float* __restrict__ x, const float* __restrict__ log_weights,
    const float* __restrict__ gleak0, const float* __restrict__ vleak0, const float* __restrict__ cm0,
    const float* __restrict__ iw0, const float* __restrict__ isig0, const float* __restrict__ imu0,
    const float* __restrict__ ierev0,
    const float* __restrict__ w0, const float* __restrict__ sig0, const float* __restrict__ mu0,
    const float* __restrict__ erev0, const float* __restrict__ gdiff0,
    const float* __restrict__ gleak1, const float* __restrict__ vleak1, const float* __restrict__ cm1,
    const float* __restrict__ iw1, const float* __restrict__ isig1, const float* __restrict__ imu1,
    const float* __restrict__ ierev1,
    const float* __restrict__ w1, const float* __restrict__ sig1, const float* __restrict__ mu1,
    const float* __restrict__ erev1, const float* __restrict__ gdiff1,
    float* __restrict__ d_out)
{
    int idx = blockIdx.x * blockDim.x + threadIdx.x;
    const float sdt = 0.40824829046386302f;  // sqrt(1/6)

    if (idx < H0 * H0) {
        int i = idx / H0;
        float s = sig0[idx], m = mu0[idx], wv = relu_(w0[idx]);
        if ((i & 3) < 2) {   // tanh path
            g_d0[idx] = make_float4(0.5f * s, -0.5f * s * m, 0.5f * wv * erev0[idx], 0.5f * wv);
        } else {             // ex2 path: y = -L2E*sig*(v-mu); sigma = 1/(1+2^y)
            g_d0[idx] = make_float4(-L2E * s, L2E * s * m, wv * erev0[idx], wv);
        }
        return;
    }
    idx -= H0 * H0;
    if (idx < H1 * H1) {
        float s = sig1[idx], m = mu1[idx], wv = relu_(w1[idx]);
        g_d1[idx] = make_float4(0.5f * s, -0.5f * s * m, 0.5f * wv * erev1[idx], 0.5f * wv);
        return;
    }
    idx -= H1 * H1;
    if (idx < H0 * H1) {
        float s = isig1[idx], m = imu1[idx], wv = relu_(iw1[idx]);
        g_din1[idx] = make_float4(0.5f * s, -0.5f * s * m, 0.5f * wv * ierev1[idx], 0.5f * wv);
        return;
    }
    idx -= H0 * H1;
    if (idx < H0) {
        float gl = relu_(gleak0[idx]);
        g_hc0[idx] = make_float4(gl * vleak0[idx], gl,
                                 1.0f / (relu_(cm0[idx]) + 1e-8f), gdiff0[idx] * sdt);
        return;
    }
    idx -= H0;
    if (idx < H1) {
        float gl = relu_(gleak1[idx]);
        g_hc1[idx] = make_float4(gl * vleak1[idx], gl,
                                 1.0f / (relu_(cm1[idx]) + 1e-8f), gdiff1[idx] * sdt);
        return;
    }
    idx -= H1;
    if (idx < H0) {   // g_sums0: PARTIAL, tanh-path i only
        float sZ = 0.f, sW = 0.f;
        for (int i = 0; i < H0; ++i) {
            if ((i & 3) < 2) {
                float wv = relu_(w0[i * H0 + idx]);
                sZ = fmaf(wv, erev0[i * H0 + idx], sZ);
                sW += wv;
            }
        }
        g_sums0[idx] = make_float2(0.5f * sZ, 0.5f * sW);
        return;
    }
    idx -= H0;
    if (idx < H1) {   // g_sums1
        float sZ = 0.f, sW = 0.f;
        for (int i = 0; i < H1; ++i) {
            float wv = relu_(w1[i * H1 + idx]);
            sZ = fmaf(wv, erev1[i * H1 + idx], sZ);
            sW += wv;
        }
        g_sums1[idx] = make_float2(0.5f * sZ, 0.5f * sW);
        return;
    }
    idx -= H1;
    if (idx < H1) {   // g_sumsin1
        float sZ = 0.f, sW = 0.f;
        for (int i = 0; i < H0; ++i) {
            float wv = relu_(iw1[i * H1 + idx]);
            sZ = fmaf(wv, ierev1[i * H1 + idx], sZ);
            sW += wv;
        }
        g_sumsin1[idx] = make_float2(0.5f * sZ, 0.5f * sW);
        return;
    }
    idx -= H1;
    if (idx < B_ * H0) {   // exact layer0 input currents
        int b = idx / H0, h = idx - b * H0;
        float an = 0.f, ad = 0.f;
        for (int i = 0; i < IN_; ++i) {
            int p = i * H0 + h;
            float y = -isig0[p] * (x[b * IN_ + i] - imu0[p]) * L2E;
            float sg = rcpf(1.f + ex2f(y));
            float a = relu_(iw0[p]) * sg;
            an = fmaf(a, ierev0[p], an);
            ad += a;
        }
        g_A0n[idx] = an;
        g_A0d[idx] = ad;
        return;
    }
    idx -= B_ * H0;
    if (idx < B_) {   // softmax weights
        float mx = -1e30f;
        for (int k = 0; k < K_; ++k) mx = fmaxf(mx, log_weights[idx * K_ + k]);
        float sum = 0.f;
        for (int k = 0; k < K_; ++k) sum += __expf(log_weights[idx * K_ + k] - mx);
        float inv = 1.0f / sum;
        for (int k = 0; k < K_; ++k)
            g_wts[idx * K_ + k] = __expf(log_weights[idx * K_ + k] - mx) * inv;
        return;
    }
    idx -= B_;
    if (idx < BK) {   // log_weights passthrough
        d_out[B_ * H1 + BK * HS + idx] = log_weights[idx];
        return;
    }
    idx -= BK;
    if (idx < B_) {
        g_cnt[idx] = 0;
        return;
    }
}

// ================= fused main kernel =================
// grid = 147 CTAs, block = 576 = 3 warpgroups x 192; group g handles i in [64g, 64g+64)
// Each 4-column chunk: cols 0,1 = tanh (MUFU rt16); cols 2,3 = ex2 (MUFU rt8) + FMA rcp.
__global__ void __launch_bounds__(NTHR, 1) main_kernel(
    const float* __restrict__ particles,
    const float* __restrict__ noise0,
    const float* __restrict__ noise1,
    float* __restrict__ out_particles,   // d_out + B_*H1
    float* __restrict__ out)             // d_out
{
    __shared__ float vsm0[RMAX][H0];     // rows are 768B: float4-aligned
    __shared__ float vsm1[RMAX][H1];
    __shared__ float pN[3][RMAX][H0];
    __shared__ float pD[3][RMAX][H0];
    __shared__ int   sflag[2];

    const int c    = blockIdx.x;
    const int tid  = threadIdx.x;
    const int row0 = c * RMAX;
    const int R    = min(RMAX, BK - row0);

    // ---------- layer 0 ----------
    {
        const int g  = tid / H0;      // 0..2
        const int h  = tid - g * H0;  // 0..191
        const int i0 = g * 64;
        const float4 hc  = g_hc0[h];
        const float2 s0s = g_sums0[h];

        float vcur[RMAX], baseN[RMAX], baseD[RMAX];
        #pragma unroll
        for (int r = 0; r < RMAX; ++r) {
            int row = min(row0 + r, BK - 1);
            float v = particles[row * HS + h];
            vcur[r] = v;
            if (g == 0) vsm0[r][h] = v;
            int b = row >> 6;
            baseN[r] = (g == 0) ? (g_A0n[b * H0 + h] + s0s.x) : 0.f;
            baseD[r] = (g == 0) ? (g_A0d[b * H0 + h] + s0s.y) : 0.f;
        }
        __syncthreads();

        const float4* pbase = &g_d0[i0 * H0 + h];

        for (int step = 0; step < UNF; ++step) {
            float accN[RMAX], accD[RMAX];
            #pragma unroll
            for (int r = 0; r < RMAX; ++r) { accN[r] = baseN[r]; accD[r] = baseD[r]; }

            // chunk of 4 columns: 2 tanh + 2 ex2-sigmoid, state via one LDS.128
            #pragma unroll 1
            for (int ii = 0; ii < 64; ii += 4) {
                float4 p0 = ldcg4(pbase + (ii + 0) * H0);
                float4 p1 = ldcg4(pbase + (ii + 1) * H0);
                float4 p2 = ldcg4(pbase + (ii + 2) * H0);
                float4 p3 = ldcg4(pbase + (ii + 3) * H0);
                const int i = i0 + ii;
                #pragma unroll
                for (int r = 0; r < RMAX; ++r) {
                    float4 v4 = *reinterpret_cast<const float4*>(&vsm0[r][i]);
                    // tanh path (cols 0,1)
                    float t0 = tanhfast(fmaf(p0.x, v4.x, p0.y));
                    float t1 = tanhfast(fmaf(p1.x, v4.y, p1.y));
                    // ex2 path (cols 2,3): sigma = 1/(1+2^y)
                    float y2 = fminf(fmaf(p2.x, v4.z, p2.y), 60.0f);
                    float y3 = fminf(fmaf(p3.x, v4.w, p3.y), 60.0f);
                    float d2 = 1.0f + ex2f(y2);
                    float d3 = 1.0f + ex2f(y3);
                    float s2 = rcp_fma(d2);
                    float s3 = rcp_fma(d3);
                    accN[r] = fmaf(p0.z, t0, accN[r]);
                    accD[r] = fmaf(p0.w, t0, accD[r]);
                    accN[r] = fmaf(p1.z, t1, accN[r]);
                    accD[r] = fmaf(p1.w, t1, accD[r]);
                    accN[r] = fmaf(p2.z, s2, accN[r]);
                    accD[r] = fmaf(p2.w, s2, accD[r]);
                    accN[r] = fmaf(p3.z, s3, accN[r]);
                    accD[r] = fmaf(p3.w, s3, accD[r]);
                }
            }
            #pragma unroll
            for (int r = 0; r < RMAX; ++r) { pN[g][r][h] = accN[r]; pD[g][r][h] = accD[r]; }
            __syncthreads();

            #pragma unroll
            for (int r = 0; r < RMAX; ++r) {
                int row = min(row0 + r, BK - 1);
                float sumN = pN[0][r][h] + pN[1][r][h] + pN[2][r][h];
                float sumD = pD[0][r][h] + pD[1][r][h] + pD[2][r][h];
                float n = noise0[(step * BK + row) * H0 + h];
                float d = fmaf(-(hc.y + sumD), vcur[r], hc.x + sumN) * hc.z;
                vcur[r] = fmaf(d, (1.0f / 6.0f), fmaf(hc.w, n, vcur[r]));
                if (g == 0) vsm0[r][h] = vcur[r];
            }
            __syncthreads();
        }
        if (g == 0) {
            #pragma unroll
            for (int r = 0; r < RMAX; ++r)
                if (r < R) out_particles[(row0 + r) * HS + h] = vcur[r];
        }
    }

    // ---------- layer 1 ----------
    const int h1  = tid & 63;
    const int seg = tid >> 6;       // 0..8; seg < RMAX handles row (row0+seg)
    {
        const float4 hc  = g_hc1[h1];
        const float2 s1s = g_sums1[h1];
        const float2 sis = g_sumsin1[h1];

        for (int idx = tid; idx < RMAX * H1; idx += NTHR) {
            int r = idx >> 6, hh = idx & 63;
            int row = min(row0 + r, BK - 1);
            vsm1[r][hh] = particles[row * HS + H0 + hh];
        }
        __syncthreads();

        float ainN = 0.f, ainD = 0.f, vc = 0.f;
        if (seg < RMAX) {
            ainN = sis.x; ainD = sis.y;
            #pragma unroll 1
            for (int i = 0; i < H0; i += 4) {
                float4 p0 = ldcg4(&g_din1[(i + 0) * H1 + h1]);
                float4 p1 = ldcg4(&g_din1[(i + 1) * H1 + h1]);
                float4 p2 = ldcg4(&g_din1[(i + 2) * H1 + h1]);
                float4 p3 = ldcg4(&g_din1[(i + 3) * H1 + h1]);
                float4 v4 = *reinterpret_cast<const float4*>(&vsm0[seg][i]);
                float t0 = tanhfast(fmaf(p0.x, v4.x, p0.y));
                float t1 = tanhfast(fmaf(p1.x, v4.y, p1.y));
                float t2 = tanhfast(fmaf(p2.x, v4.z, p2.y));
                float t3 = tanhfast(fmaf(p3.x, v4.w, p3.y));
                ainN = fmaf(p0.z, t0, ainN); ainD = fmaf(p0.w, t0, ainD);
                ainN = fmaf(p1.z, t1, ainN); ainD = fmaf(p1.w, t1, ainD);
                ainN = fmaf(p2.z, t2, ainN); ainD = fmaf(p2.w, t2, ainD);
                ainN = fmaf(p3.z, t3, ainN); ainD = fmaf(p3.w, t3, ainD);
            }
            vc = vsm1[seg][h1];
        }

        for (int step = 0; step < UNF; ++step) {
            float nv = 0.f;
            if (seg < RMAX) {
                float accN = ainN + s1s.x;
                float accD = ainD + s1s.y;
                #pragma unroll 1
                for (int i = 0; i < H1; i += 4) {
                    float4 p0 = g_d1[(i + 0) * H1 + h1];   // 64KB, L1-resident
                    float4 p1 = g_d1[(i + 1) * H1 + h1];
                    float4 p2 = g_d1[(i + 2) * H1 + h1];
                    float4 p3 = g_d1[(i + 3) * H1 + h1];
                    float4 v4 = *reinterpret_cast<const float4*>(&vsm1[seg][i]);
                    float t0 = tanhfast(fmaf(p0.x, v4.x, p0.y));
                    float t1 = tanhfast(fmaf(p1.x, v4.y, p1.y));
                    float t2 = tanhfast(fmaf(p2.x, v4.z, p2.y));
                    float t3 = tanhfast(fmaf(p3.x, v4.w, p3.y));
                    accN = fmaf(p0.z, t0, accN); accD = fmaf(p0.w, t0, accD);
                    accN = fmaf(p1.z, t1, accN); accD = fmaf(p1.w, t1, accD);
                    accN = fmaf(p2.z, t2, accN); accD = fmaf(p2.w, t2, accD);
                    accN = fmaf(p3.z, t3, accN); accD = fmaf(p3.w, t3, accD);
                }
                int row = min(row0 + seg, BK - 1);
                float n = noise1[(step * BK + row) * H1 + h1];
                float d = fmaf(-(hc.y + accD), vc, hc.x + accN) * hc.z;
                nv = fmaf(d, (1.0f / 6.0f), fmaf(hc.w, n, vc));
            }
            __syncthreads();
            if (seg < RMAX) { vsm1[seg][h1] = nv; vc = nv; }
            __syncthreads();
        }

        if (seg < RMAX) {
            int row = row0 + seg;
            if (row < BK) {
                out_particles[row * HS + H0 + h1] = vc;
                g_s1[row * H1 + h1] = vc;
            }
        }
    }

    // ---------- output (last CTA per b reduces) ----------
    __threadfence();
    __syncthreads();
    if (tid == 0) {
        sflag[0] = -1; sflag[1] = -1;
        int b0 = row0 >> 6, b1 = (row0 + R - 1) >> 6;
        int k = 0;
        for (int b = b0; b <= b1; ++b) {
            int cf = (b * K_) / RMAX;
            int cl = min(NCTA - 1, (b * K_ + 63) / RMAX);
            int tgt = cl - cf + 1;
            int old = atomicAdd(&g_cnt[b], 1);
            sflag[k++] = (old == tgt - 1) ? b : -1;
        }
    }
    __syncthreads();
    __threadfence();
    #pragma unroll
    for (int k = 0; k < 2; ++k) {
        int b = sflag[k];
        if (b >= 0 && tid < K_) {
            float acc = 0.f;
            #pragma unroll 8
            for (int kk = 0; kk < K_; ++kk)
                acc = fmaf(g_wts[b * K_ + kk], __ldcg(&g_s1[(b * K_ + kk) * H1 + tid]), acc);
            out[b * H1 + tid] = acc;
        }
    }
}

// ================= launch =================
extern "C" void kernel_launch(void* const* d_in, const int* in_sizes, int n_in,
                              void* d_out, int out_size)
{
    const float* x           = (const float*)d_in[0];
    const float* particles   = (const float*)d_in[1];
    const float* log_weights = (const float*)d_in[2];
    const float* noise0      = (const float*)d_in[3];
    const float* noise1      = (const float*)d_in[4];

    const int total = H0*H0 + H1*H1 + H0*H1 + H0 + H1 + H0 + H1 + H1
                    + B_*H0 + B_ + BK + B_;
    precompute_kernel<<<(total + 255) / 256, 256>>>(
        x, log_weights,
        (const float*)d_in[5],  (const float*)d_in[6],  (const float*)d_in[7],
        (const float*)d_in[8],  (const float*)d_in[9],  (const float*)d_in[10],
        (const float*)d_in[11],
        (const float*)d_in[12], (const float*)d_in[13], (const float*)d_in[14],
        (const float*)d_in[15], (const float*)d_in[16],
        (const float*)d_in[17], (const float*)d_in[18], (const float*)d_in[19],
        (const float*)d_in[20], (const float*)d_in[21], (const float*)d_in[22],
        (const float*)d_in[23],
        (const float*)d_in[24], (const float*)d_in[25], (const float*)d_in[26],
        (const float*)d_in[27], (const float*)d_in[28],
        (float*)d_out);

    float* out = (float*)d_out;
    main_kernel<<<NCTA, NTHR>>>(particles, noise0, noise1, out + B_ * H1, out);
}

// round 14
// speedup vs baseline: 1.1728x; 1.1728x over previous
#include <cuda_runtime.h>

// Problem constants
#define B_   16
#define K_   64
#define BK   1024
#define IN_  128
#define H0   192
#define H1   64
#define UNF  6
#define HS   (H0 + H1)        // 256
#define L2E  1.4426950408889634f
#define RMAX 7
#define NCTA 147              // ceil(1024 / 7)
#define NTHR 576              // 3 warpgroups of 192

// -------- device scratch --------
// tanh-folded params: {0.5*sig, -0.5*sig*mu, 0.5*relu(w)*erev, 0.5*relu(w)}
__device__ float4 g_d0[H0 * H0];
__device__ float4 g_d1[H1 * H1];
__device__ float4 g_din1[H0 * H1];
__device__ float4 g_hc0[H0];       // {gl*vleak, gl, 1/(relu(cm)+eps), gdiff*sqrt(dt)}
__device__ float4 g_hc1[H1];
__device__ float2 g_sums0[H0];     // exact column sums {0.5*wz, 0.5*ww}
__device__ float2 g_sums1[H1];
__device__ float2 g_sumsin1[H1];
__device__ float  g_A0n[B_ * H0];
__device__ float  g_A0d[B_ * H0];
__device__ float  g_wts[B_ * K_];
__device__ float  g_s1[BK * H1];
__device__ int    g_cnt[B_];

__device__ __forceinline__ float tanhfast(float x) {
    float r; asm("tanh.approx.f32 %0, %1;" : "=f"(r) : "f"(x)); return r;
}
__device__ __forceinline__ float ex2f(float x) {
    float r; asm("ex2.approx.f32 %0, %1;" : "=f"(r) : "f"(x)); return r;
}
__device__ __forceinline__ float rcpf(float x) {
    float r; asm("rcp.approx.f32 %0, %1;" : "=f"(r) : "f"(x)); return r;
}
__device__ __forceinline__ float relu_(float x) { return x > 0.f ? x : 0.f; }
__device__ __forceinline__ float4 ldcg4(const float4* p) {
    float4 v;
    asm volatile("ld.global.cg.v4.f32 {%0,%1,%2,%3}, [%4];"
                 : "=f"(v.x), "=f"(v.y), "=f"(v.z), "=f"(v.w) : "l"(p));
    return v;
}

// ================= precompute =================
__global__ void precompute_kernel(
    const float* __restrict__ x, const float* __restrict__ log_weights,
    const float* __restrict__ gleak0, const float* __restrict__ vleak0, const float* __restrict__ cm0,
    const float* __restrict__ iw0, const float* __restrict__ isig0, const float* __restrict__ imu0,
    const float* __restrict__ ierev0,
    const float* __restrict__ w0, const float* __restrict__ sig0, const float* __restrict__ mu0,
    const float* __restrict__ erev0, const float* __restrict__ gdiff0,
    const float* __restrict__ gleak1, const float* __restrict__ vleak1, const float* __restrict__ cm1,
    const float* __restrict__ iw1, const float* __restrict__ isig1, const float* __restrict__ imu1,
    const float* __restrict__ ierev1,
    const float* __restrict__ w1, const float* __restrict__ sig1, const float* __restrict__ mu1,
    const float* __restrict__ erev1, const float* __restrict__ gdiff1,
    float* __restrict__ d_out)
{
    int idx = blockIdx.x * blockDim.x + threadIdx.x;
    const float sdt = 0.40824829046386302f;  // sqrt(1/6)

    if (idx < H0 * H0) {
        float s = sig0[idx], m = mu0[idx], wv = relu_(w0[idx]);
        g_d0[idx] = make_float4(0.5f * s, -0.5f * s * m, 0.5f * wv * erev0[idx], 0.5f * wv);
        return;
    }
    idx -= H0 * H0;
    if (idx < H1 * H1) {
        float s = sig1[idx], m = mu1[idx], wv = relu_(w1[idx]);
        g_d1[idx] = make_float4(0.5f * s, -0.5f * s * m, 0.5f * wv * erev1[idx], 0.5f * wv);
        return;
    }
    idx -= H1 * H1;
    if (idx < H0 * H1) {
        float s = isig1[idx], m = imu1[idx], wv = relu_(iw1[idx]);
        g_din1[idx] = make_float4(0.5f * s, -0.5f * s * m, 0.5f * wv * ierev1[idx], 0.5f * wv);
        return;
    }
    idx -= H0 * H1;
    if (idx < H0) {
        float gl = relu_(gleak0[idx]);
        g_hc0[idx] = make_float4(gl * vleak0[idx], gl,
                                 1.0f / (relu_(cm0[idx]) + 1e-8f), gdiff0[idx] * sdt);
        return;
    }
    idx -= H0;
    if (idx < H1) {
        float gl = relu_(gleak1[idx]);
        g_hc1[idx] = make_float4(gl * vleak1[idx], gl,
                                 1.0f / (relu_(cm1[idx]) + 1e-8f), gdiff1[idx] * sdt);
        return;
    }
    idx -= H1;
    if (idx < H0) {   // g_sums0
        float sZ = 0.f, sW = 0.f;
        for (int i = 0; i < H0; ++i) {
            float wv = relu_(w0[i * H0 + idx]);
            sZ = fmaf(wv, erev0[i * H0 + idx], sZ);
            sW += wv;
        }
        g_sums0[idx] = make_float2(0.5f * sZ, 0.5f * sW);
        return;
    }
    idx -= H0;
    if (idx < H1) {   // g_sums1
        float sZ = 0.f, sW = 0.f;
        for (int i = 0; i < H1; ++i) {
            float wv = relu_(w1[i * H1 + idx]);
            sZ = fmaf(wv, erev1[i * H1 + idx], sZ);
            sW += wv;
        }
        g_sums1[idx] = make_float2(0.5f * sZ, 0.5f * sW);
        return;
    }
    idx -= H1;
    if (idx < H1) {   // g_sumsin1
        float sZ = 0.f, sW = 0.f;
        for (int i = 0; i < H0; ++i) {
            float wv = relu_(iw1[i * H1 + idx]);
            sZ = fmaf(wv, ierev1[i * H1 + idx], sZ);
            sW += wv;
        }
        g_sumsin1[idx] = make_float2(0.5f * sZ, 0.5f * sW);
        return;
    }
    idx -= H1;
    if (idx < B_ * H0) {   // exact layer0 input currents
        int b = idx / H0, h = idx - b * H0;
        float an = 0.f, ad = 0.f;
        for (int i = 0; i < IN_; ++i) {
            int p = i * H0 + h;
            float y = -isig0[p] * (x[b * IN_ + i] - imu0[p]) * L2E;
            float sg = rcpf(1.f + ex2f(y));
            float a = relu_(iw0[p]) * sg;
            an = fmaf(a, ierev0[p], an);
            ad += a;
        }
        g_A0n[idx] = an;
        g_A0d[idx] = ad;
        return;
    }
    idx -= B_ * H0;
    if (idx < B_) {   // softmax weights
        float mx = -1e30f;
        for (int k = 0; k < K_; ++k) mx = fmaxf(mx, log_weights[idx * K_ + k]);
        float sum = 0.f;
        for (int k = 0; k < K_; ++k) sum += __expf(log_weights[idx * K_ + k] - mx);
        float inv = 1.0f / sum;
        for (int k = 0; k < K_; ++k)
            g_wts[idx * K_ + k] = __expf(log_weights[idx * K_ + k] - mx) * inv;
        return;
    }
    idx -= B_;
    if (idx < BK) {   // log_weights passthrough
        d_out[B_ * H1 + BK * HS + idx] = log_weights[idx];
        return;
    }
    idx -= BK;
    if (idx < B_) {
        g_cnt[idx] = 0;
        return;
    }
}

// ================= fused main kernel =================
// grid = 147 CTAs, block = 576 = 3 warpgroups x 192; group g handles i in [64g, 64g+64)
__global__ void __launch_bounds__(NTHR, 1) main_kernel(
    const float* __restrict__ particles,
    const float* __restrict__ noise0,
    const float* __restrict__ noise1,
    float* __restrict__ out_particles,   // d_out + B_*H1
    float* __restrict__ out)             // d_out
{
    __shared__ float vsm0[RMAX][H0];
    __shared__ float vsm1[RMAX][H1];
    __shared__ float pN[3][RMAX][H0];
    __shared__ float pD[3][RMAX][H0];
    __shared__ int   sflag[2];

    const int c    = blockIdx.x;
    const int tid  = threadIdx.x;
    const int row0 = c * RMAX;
    const int R    = min(RMAX, BK - row0);

    // ---------- layer 0 ----------
    {
        const int g  = tid / H0;      // 0..2
        const int h  = tid - g * H0;  // 0..191
        const int i0 = g * 64;
        const float4 hc  = g_hc0[h];
        const float2 s0s = g_sums0[h];

        float vcur[RMAX], baseN[RMAX], baseD[RMAX];
        #pragma unroll
        for (int r = 0; r < RMAX; ++r) {
            int row = min(row0 + r, BK - 1);
            float v = particles[row * HS + h];
            vcur[r] = v;
            if (g == 0) vsm0[r][h] = v;
            int b = row >> 6;
            baseN[r] = (g == 0) ? (g_A0n[b * H0 + h] + s0s.x) : 0.f;
            baseD[r] = (g == 0) ? (g_A0d[b * H0 + h] + s0s.y) : 0.f;
        }
        __syncthreads();

        const float4* pbase = &g_d0[i0 * H0 + h];

        for (int step = 0; step < UNF; ++step) {
            float accN[RMAX], accD[RMAX];
            #pragma unroll
            for (int r = 0; r < RMAX; ++r) { accN[r] = baseN[r]; accD[r] = baseD[r]; }

            // i-loop, 4-way batched loads (MLP=4), L1 bypass on the param stream
            #pragma unroll 1
            for (int ii = 0; ii < 64; ii += 4) {
                float4 p0 = ldcg4(pbase + (ii + 0) * H0);
                float4 p1 = ldcg4(pbase + (ii + 1) * H0);
                float4 p2 = ldcg4(pbase + (ii + 2) * H0);
                float4 p3 = ldcg4(pbase + (ii + 3) * H0);
                const int i = i0 + ii;
                #pragma unroll
                for (int r = 0; r < RMAX; ++r) {
                    float t0 = tanhfast(fmaf(p0.x, vsm0[r][i + 0], p0.y));
                    float t1 = tanhfast(fmaf(p1.x, vsm0[r][i + 1], p1.y));
                    float t2 = tanhfast(fmaf(p2.x, vsm0[r][i + 2], p2.y));
                    float t3 = tanhfast(fmaf(p3.x, vsm0[r][i + 3], p3.y));
                    accN[r] = fmaf(p0.z, t0, accN[r]);
                    accD[r] = fmaf(p0.w, t0, accD[r]);
                    accN[r] = fmaf(p1.z, t1, accN[r]);
                    accD[r] = fmaf(p1.w, t1, accD[r]);
                    accN[r] = fmaf(p2.z, t2, accN[r]);
                    accD[r] = fmaf(p2.w, t2, accD[r]);
                    accN[r] = fmaf(p3.z, t3, accN[r]);
                    accD[r] = fmaf(p3.w, t3, accD[r]);
                }
            }
            #pragma unroll
            for (int r = 0; r < RMAX; ++r) { pN[g][r][h] = accN[r]; pD[g][r][h] = accD[r]; }
            __syncthreads();

            // every group redundantly computes the identical update; only g0 writes vsm0
            #pragma unroll
            for (int r = 0; r < RMAX; ++r) {
                int row = min(row0 + r, BK - 1);
                float sumN = pN[0][r][h] + pN[1][r][h] + pN[2][r][h];
                float sumD = pD[0][r][h] + pD[1][r][h] + pD[2][r][h];
                float n = noise0[(step * BK + row) * H0 + h];
                float d = fmaf(-(hc.y + sumD), vcur[r], hc.x + sumN) * hc.z;
                vcur[r] = fmaf(d, (1.0f / 6.0f), fmaf(hc.w, n, vcur[r]));
                if (g == 0) vsm0[r][h] = vcur[r];
            }
            __syncthreads();
        }
        if (g == 0) {
            #pragma unroll
            for (int r = 0; r < RMAX; ++r)
                if (r < R) out_particles[(row0 + r) * HS + h] = vcur[r];
        }
    }

    // ---------- layer 1 ----------
    const int h1  = tid & 63;
    const int seg = tid >> 6;       // 0..8; seg < RMAX handles row (row0+seg)
    {
        const float4 hc  = g_hc1[h1];
        const float2 s1s = g_sums1[h1];
        const float2 sis = g_sumsin1[h1];

        for (int idx = tid; idx < RMAX * H1; idx += NTHR) {
            int r = idx >> 6, hh = idx & 63;
            int row = min(row0 + r, BK - 1);
            vsm1[r][hh] = particles[row * HS + H0 + hh];
        }
        __syncthreads();

        float ainN = 0.f, ainD = 0.f, vc = 0.f;
        if (seg < RMAX) {
            ainN = sis.x; ainD = sis.y;
            #pragma unroll 1
            for (int i = 0; i < H0; i += 4) {
                float4 p0 = ldcg4(&g_din1[(i + 0) * H1 + h1]);
                float4 p1 = ldcg4(&g_din1[(i + 1) * H1 + h1]);
                float4 p2 = ldcg4(&g_din1[(i + 2) * H1 + h1]);
                float4 p3 = ldcg4(&g_din1[(i + 3) * H1 + h1]);
                float t0 = tanhfast(fmaf(p0.x, vsm0[seg][i + 0], p0.y));
                float t1 = tanhfast(fmaf(p1.x, vsm0[seg][i + 1], p1.y));
                float t2 = tanhfast(fmaf(p2.x, vsm0[seg][i + 2], p2.y));
                float t3 = tanhfast(fmaf(p3.x, vsm0[seg][i + 3], p3.y));
                ainN = fmaf(p0.z, t0, ainN); ainD = fmaf(p0.w, t0, ainD);
                ainN = fmaf(p1.z, t1, ainN); ainD = fmaf(p1.w, t1, ainD);
                ainN = fmaf(p2.z, t2, ainN); ainD = fmaf(p2.w, t2, ainD);
                ainN = fmaf(p3.z, t3, ainN); ainD = fmaf(p3.w, t3, ainD);
            }
            vc = vsm1[seg][h1];
        }

        for (int step = 0; step < UNF; ++step) {
            float nv = 0.f;
            if (seg < RMAX) {
                float accN = ainN + s1s.x;
                float accD = ainD + s1s.y;
                #pragma unroll 4
                for (int i = 0; i < H1; ++i) {
                    float4 p = g_d1[i * H1 + h1];   // 64KB, L1-resident, reused 6x
                    float t = tanhfast(fmaf(p.x, vsm1[seg][i], p.y));
                    accN = fmaf(p.z, t, accN);
                    accD = fmaf(p.w, t, accD);
                }
                int row = min(row0 + seg, BK - 1);
                float n = noise1[(step * BK + row) * H1 + h1];
                float d = fmaf(-(hc.y + accD), vc, hc.x + accN) * hc.z;
                nv = fmaf(d, (1.0f / 6.0f), fmaf(hc.w, n, vc));
            }
            __syncthreads();
            if (seg < RMAX) { vsm1[seg][h1] = nv; vc = nv; }
            __syncthreads();
        }

        if (seg < RMAX) {
            int row = row0 + seg;
            if (row < BK) {
                out_particles[row * HS + H0 + h1] = vc;
                g_s1[row * H1 + h1] = vc;
            }
        }
    }

    // ---------- output (last CTA per b reduces) ----------
    __threadfence();
    __syncthreads();
    if (tid == 0) {
        sflag[0] = -1; sflag[1] = -1;
        int b0 = row0 >> 6, b1 = (row0 + R - 1) >> 6;
        int k = 0;
        for (int b = b0; b <= b1; ++b) {
            int cf = (b * K_) / RMAX;
            int cl = min(NCTA - 1, (b * K_ + 63) / RMAX);
            int tgt = cl - cf + 1;
            int old = atomicAdd(&g_cnt[b], 1);
            sflag[k++] = (old == tgt - 1) ? b : -1;
        }
    }
    __syncthreads();
    __threadfence();
    #pragma unroll
    for (int k = 0; k < 2; ++k) {
        int b = sflag[k];
        if (b >= 0 && tid < K_) {
            float acc = 0.f;
            #pragma unroll 8
            for (int kk = 0; kk < K_; ++kk)
                acc = fmaf(g_wts[b * K_ + kk], __ldcg(&g_s1[(b * K_ + kk) * H1 + tid]), acc);
            out[b * H1 + tid] = acc;
        }
    }
}

// ================= launch =================
extern "C" void kernel_launch(void* const* d_in, const int* in_sizes, int n_in,
                              void* d_out, int out_size)
{
    const float* x           = (const float*)d_in[0];
    const float* particles   = (const float*)d_in[1];
    const float* log_weights = (const float*)d_in[2];
    const float* noise0      = (const float*)d_in[3];
    const float* noise1      = (const float*)d_in[4];

    const int total = H0*H0 + H1*H1 + H0*H1 + H0 + H1 + H0 + H1 + H1
                    + B_*H0 + B_ + BK + B_;
    precompute_kernel<<<(total + 255) / 256, 256>>>(
        x, log_weights,
        (const float*)d_in[5],  (const float*)d_in[6],  (const float*)d_in[7],
        (const float*)d_in[8],  (const float*)d_in[9],  (const float*)d_in[10],
        (const float*)d_in[11],
        (const float*)d_in[12], (const float*)d_in[13], (const float*)d_in[14],
        (const float*)d_in[15], (const float*)d_in[16],
        (const float*)d_in[17], (const float*)d_in[18], (const float*)d_in[19],
        (const float*)d_in[20], (const float*)d_in[21], (const float*)d_in[22],
        (const float*)d_in[23],
        (const float*)d_in[24], (const float*)d_in[25], (const float*)d_in[26],
        (const float*)d_in[27], (const float*)d_in[28],
        (float*)d_out);

    float* out = (float*)d_out;
    main_kernel<<<NCTA, NTHR>>>(particles, noise0, noise1, out + B_ * H1, out);
}

// round 16
// speedup vs baseline: 1.1865x; 1.0117x over previous
#include <cuda_runtime.h>

// Problem constants
#define B_   16
#define K_   64
#define BK   1024
#define IN_  128
#define H0   192
#define H1   64
#define UNF  6
#define HS   (H0 + H1)        // 256
#define L2E  1.4426950408889634f
#define RMAX 7
#define NCTA 147              // ceil(1024 / 7)
#define NTHR 576              // 18 warps

// -------- device scratch --------
// tanh-folded params: {0.5*sig, -0.5*sig*mu, 0.5*relu(w)*erev, 0.5*relu(w)}
__device__ float4 g_d0[H0 * H0];
__device__ float4 g_d1[H1 * H1];
__device__ float4 g_din1[H0 * H1];
__device__ float4 g_hc0[H0];       // {gl*vleak, gl, 1/(relu(cm)+eps), gdiff*sqrt(dt)}
__device__ float4 g_hc1[H1];
__device__ float2 g_sums0[H0];     // exact column sums {0.5*wz, 0.5*ww}
__device__ float2 g_sums1[H1];
__device__ float2 g_sumsin1[H1];
__device__ float  g_A0n[B_ * H0];
__device__ float  g_A0d[B_ * H0];
__device__ float  g_wts[B_ * K_];
__device__ float  g_s1[BK * H1];
__device__ int    g_cnt[B_];

__device__ __forceinline__ float tanhfast(float x) {
    float r; asm("tanh.approx.f32 %0, %1;" : "=f"(r) : "f"(x)); return r;
}
__device__ __forceinline__ float ex2f(float x) {
    float r; asm("ex2.approx.f32 %0, %1;" : "=f"(r) : "f"(x)); return r;
}
__device__ __forceinline__ float rcpf(float x) {
    float r; asm("rcp.approx.f32 %0, %1;" : "=f"(r) : "f"(x)); return r;
}
__device__ __forceinline__ float relu_(float x) { return x > 0.f ? x : 0.f; }
__device__ __forceinline__ float4 ldcg4(const float4* p) {
    float4 v;
    asm volatile("ld.global.cg.v4.f32 {%0,%1,%2,%3}, [%4];"
                 : "=f"(v.x), "=f"(v.y), "=f"(v.z), "=f"(v.w) : "l"(p));
    return v;
}

// ================= precompute =================
__global__ void precompute_kernel(
    const float* __restrict__ x, const float* __restrict__ log_weights,
    const float* __restrict__ gleak0, const float* __restrict__ vleak0, const float* __restrict__ cm0,
    const float* __restrict__ iw0, const float* __restrict__ isig0, const float* __restrict__ imu0,
    const float* __restrict__ ierev0,
    const float* __restrict__ w0, const float* __restrict__ sig0, const float* __restrict__ mu0,
    const float* __restrict__ erev0, const float* __restrict__ gdiff0,
    const float* __restrict__ gleak1, const float* __restrict__ vleak1, const float* __restrict__ cm1,
    const float* __restrict__ iw1, const float* __restrict__ isig1, const float* __restrict__ imu1,
    const float* __restrict__ ierev1,
    const float* __restrict__ w1, const float* __restrict__ sig1, const float* __restrict__ mu1,
    const float* __restrict__ erev1, const float* __restrict__ gdiff1,
    float* __restrict__ d_out)
{
    int idx = blockIdx.x * blockDim.x + threadIdx.x;
    const float sdt = 0.40824829046386302f;  // sqrt(1/6)

    if (idx < H0 * H0) {
        float s = sig0[idx], m = mu0[idx], wv = relu_(w0[idx]);
        g_d0[idx] = make_float4(0.5f * s, -0.5f * s * m, 0.5f * wv * erev0[idx], 0.5f * wv);
        return;
    }
    idx -= H0 * H0;
    if (idx < H1 * H1) {
        float s = sig1[idx], m = mu1[idx], wv = relu_(w1[idx]);
        g_d1[idx] = make_float4(0.5f * s, -0.5f * s * m, 0.5f * wv * erev1[idx], 0.5f * wv);
        return;
    }
    idx -= H1 * H1;
    if (idx < H0 * H1) {
        float s = isig1[idx], m = imu1[idx], wv = relu_(iw1[idx]);
        g_din1[idx] = make_float4(0.5f * s, -0.5f * s * m, 0.5f * wv * ierev1[idx], 0.5f * wv);
        return;
    }
    idx -= H0 * H1;
    if (idx < H0) {
        float gl = relu_(gleak0[idx]);
        g_hc0[idx] = make_float4(gl * vleak0[idx], gl,
                                 1.0f / (relu_(cm0[idx]) + 1e-8f), gdiff0[idx] * sdt);
        return;
    }
    idx -= H0;
    if (idx < H1) {
        float gl = relu_(gleak1[idx]);
        g_hc1[idx] = make_float4(gl * vleak1[idx], gl,
                                 1.0f / (relu_(cm1[idx]) + 1e-8f), gdiff1[idx] * sdt);
        return;
    }
    idx -= H1;
    if (idx < H0) {   // g_sums0
        float sZ = 0.f, sW = 0.f;
        for (int i = 0; i < H0; ++i) {
            float wv = relu_(w0[i * H0 + idx]);
            sZ = fmaf(wv, erev0[i * H0 + idx], sZ);
            sW += wv;
        }
        g_sums0[idx] = make_float2(0.5f * sZ, 0.5f * sW);
        return;
    }
    idx -= H0;
    if (idx < H1) {   // g_sums1
        float sZ = 0.f, sW = 0.f;
        for (int i = 0; i < H1; ++i) {
            float wv = relu_(w1[i * H1 + idx]);
            sZ = fmaf(wv, erev1[i * H1 + idx], sZ);
            sW += wv;
        }
        g_sums1[idx] = make_float2(0.5f * sZ, 0.5f * sW);
        return;
    }
    idx -= H1;
    if (idx < H1) {   // g_sumsin1
        float sZ = 0.f, sW = 0.f;
        for (int i = 0; i < H0; ++i) {
            float wv = relu_(iw1[i * H1 + idx]);
            sZ = fmaf(wv, ierev1[i * H1 + idx], sZ);
            sW += wv;
        }
        g_sumsin1[idx] = make_float2(0.5f * sZ, 0.5f * sW);
        return;
    }
    idx -= H1;
    if (idx < B_ * H0) {   // exact layer0 input currents
        int b = idx / H0, h = idx - b * H0;
        float an = 0.f, ad = 0.f;
        for (int i = 0; i < IN_; ++i) {
            int p = i * H0 + h;
            float y = -isig0[p] * (x[b * IN_ + i] - imu0[p]) * L2E;
            float sg = rcpf(1.f + ex2f(y));
            float a = relu_(iw0[p]) * sg;
            an = fmaf(a, ierev0[p], an);
            ad += a;
        }
        g_A0n[idx] = an;
        g_A0d[idx] = ad;
        return;
    }
    idx -= B_ * H0;
    if (idx < B_) {   // softmax weights
        float mx = -1e30f;
        for (int k = 0; k < K_; ++k) mx = fmaxf(mx, log_weights[idx * K_ + k]);
        float sum = 0.f;
        for (int k = 0; k < K_; ++k) sum += __expf(log_weights[idx * K_ + k] - mx);
        float inv = 1.0f / sum;
        for (int k = 0; k < K_; ++k)
            g_wts[idx * K_ + k] = __expf(log_weights[idx * K_ + k] - mx) * inv;
        return;
    }
    idx -= B_;
    if (idx < BK) {   // log_weights passthrough
        d_out[B_ * H1 + BK * HS + idx] = log_weights[idx];
        return;
    }
    idx -= BK;
    if (idx < B_) {
        g_cnt[idx] = 0;
        return;
    }
}

// ================= fused main kernel =================
// grid = 147 CTAs, block = 576 = 18 warps.
// Layer0 SMSP-balanced mapping: warp w -> h-slice s=w%6 (h in [32s,32s+32)),
// position p=w/6. The 192 i-columns per h-slice are split (60,72,60) for
// s in {0,1,4,5} and (72,48,72) for s in {2,3}, which gives every SMSP
// (wid%4; 5/5/4/4 warps) exactly 288 columns -> balanced MUFU load.
__global__ void __launch_bounds__(NTHR, 1) main_kernel(
    const float* __restrict__ particles,
    const float* __restrict__ noise0,
    const float* __restrict__ noise1,
    float* __restrict__ out_particles,   // d_out + B_*H1
    float* __restrict__ out)             // d_out
{
    __shared__ float vsm0[RMAX][H0];
    __shared__ float vsm1[RMAX][H1];
    __shared__ float pN[3][RMAX][H0];
    __shared__ float pD[3][RMAX][H0];
    __shared__ int   sflag[2];

    const int c    = blockIdx.x;
    const int tid  = threadIdx.x;
    const int row0 = c * RMAX;
    const int R    = min(RMAX, BK - row0);

    // ---------- layer 0 ----------
    {
        const int wid  = tid >> 5;
        const int lane = tid & 31;
        const int s    = wid % 6;          // h-slice
        const int pos  = wid / 6;          // 0..2 partial position
        const int h    = s * 32 + lane;    // 0..191
        const bool mid = (s == 2 || s == 3);
        const int b0   = mid ? 72 : 60;
        const int b1   = mid ? 120 : 132;
        const int cs   = (pos == 0) ? 0  : (pos == 1 ? b0 : b1);
        const int ce   = (pos == 0) ? b0 : (pos == 1 ? b1 : 192);

        const float4 hc  = g_hc0[h];
        const float2 s0s = g_sums0[h];

        float vcur[RMAX], baseN[RMAX], baseD[RMAX];
        #pragma unroll
        for (int r = 0; r < RMAX; ++r) {
            int row = min(row0 + r, BK - 1);
            float v = particles[row * HS + h];
            vcur[r] = v;
            if (pos == 0) vsm0[r][h] = v;
            int b = row >> 6;
            baseN[r] = (pos == 0) ? (g_A0n[b * H0 + h] + s0s.x) : 0.f;
            baseD[r] = (pos == 0) ? (g_A0d[b * H0 + h] + s0s.y) : 0.f;
        }
        __syncthreads();

        const float4* pb = &g_d0[h];

        for (int step = 0; step < UNF; ++step) {
            float accN[RMAX], accD[RMAX];
            #pragma unroll
            for (int r = 0; r < RMAX; ++r) { accN[r] = baseN[r]; accD[r] = baseD[r]; }

            // i-loop over this warp's balanced range, 4-way batched loads
            #pragma unroll 1
            for (int ii = cs; ii < ce; ii += 4) {
                float4 p0 = ldcg4(pb + (ii + 0) * H0);
                float4 p1 = ldcg4(pb + (ii + 1) * H0);
                float4 p2 = ldcg4(pb + (ii + 2) * H0);
                float4 p3 = ldcg4(pb + (ii + 3) * H0);
                #pragma unroll
                for (int r = 0; r < RMAX; ++r) {
                    float t0 = tanhfast(fmaf(p0.x, vsm0[r][ii + 0], p0.y));
                    float t1 = tanhfast(fmaf(p1.x, vsm0[r][ii + 1], p1.y));
                    float t2 = tanhfast(fmaf(p2.x, vsm0[r][ii + 2], p2.y));
                    float t3 = tanhfast(fmaf(p3.x, vsm0[r][ii + 3], p3.y));
                    accN[r] = fmaf(p0.z, t0, accN[r]);
                    accD[r] = fmaf(p0.w, t0, accD[r]);
                    accN[r] = fmaf(p1.z, t1, accN[r]);
                    accD[r] = fmaf(p1.w, t1, accD[r]);
                    accN[r] = fmaf(p2.z, t2, accN[r]);
                    accD[r] = fmaf(p2.w, t2, accD[r]);
                    accN[r] = fmaf(p3.z, t3, accN[r]);
                    accD[r] = fmaf(p3.w, t3, accD[r]);
                }
            }
            #pragma unroll
            for (int r = 0; r < RMAX; ++r) { pN[pos][r][h] = accN[r]; pD[pos][r][h] = accD[r]; }
            __syncthreads();

            // every warp redundantly computes the identical update; only pos0 writes vsm0
            #pragma unroll
            for (int r = 0; r < RMAX; ++r) {
                int row = min(row0 + r, BK - 1);
                float sumN = pN[0][r][h] + pN[1][r][h] + pN[2][r][h];
                float sumD = pD[0][r][h] + pD[1][r][h] + pD[2][r][h];
                float n = noise0[(step * BK + row) * H0 + h];
                float d = fmaf(-(hc.y + sumD), vcur[r], hc.x + sumN) * hc.z;
                vcur[r] = fmaf(d, (1.0f / 6.0f), fmaf(hc.w, n, vcur[r]));
                if (pos == 0) vsm0[r][h] = vcur[r];
            }
            __syncthreads();
        }
        if (pos == 0) {
            #pragma unroll
            for (int r = 0; r < RMAX; ++r)
                if (r < R) out_particles[(row0 + r) * HS + h] = vcur[r];
        }
    }

    // ---------- layer 1 ----------
    const int h1  = tid & 63;
    const int seg = tid >> 6;       // 0..8; seg < RMAX handles row (row0+seg)
    {
        const float4 hc  = g_hc1[h1];
        const float2 s1s = g_sums1[h1];
        const float2 sis = g_sumsin1[h1];

        for (int idx = tid; idx < RMAX * H1; idx += NTHR) {
            int r = idx >> 6, hh = idx & 63;
            int row = min(row0 + r, BK - 1);
            vsm1[r][hh] = particles[row * HS + H0 + hh];
        }
        __syncthreads();

        float ainN = 0.f, ainD = 0.f, vc = 0.f;
        if (seg < RMAX) {
            ainN = sis.x; ainD = sis.y;
            #pragma unroll 1
            for (int i = 0; i < H0; i += 4) {
                float4 p0 = ldcg4(&g_din1[(i + 0) * H1 + h1]);
                float4 p1 = ldcg4(&g_din1[(i + 1) * H1 + h1]);
                float4 p2 = ldcg4(&g_din1[(i + 2) * H1 + h1]);
                float4 p3 = ldcg4(&g_din1[(i + 3) * H1 + h1]);
                float t0 = tanhfast(fmaf(p0.x, vsm0[seg][i + 0], p0.y));
                float t1 = tanhfast(fmaf(p1.x, vsm0[seg][i + 1], p1.y));
                float t2 = tanhfast(fmaf(p2.x, vsm0[seg][i + 2], p2.y));
                float t3 = tanhfast(fmaf(p3.x, vsm0[seg][i + 3], p3.y));
                ainN = fmaf(p0.z, t0, ainN); ainD = fmaf(p0.w, t0, ainD);
                ainN = fmaf(p1.z, t1, ainN); ainD = fmaf(p1.w, t1, ainD);
                ainN = fmaf(p2.z, t2, ainN); ainD = fmaf(p2.w, t2, ainD);
                ainN = fmaf(p3.z, t3, ainN); ainD = fmaf(p3.w, t3, ainD);
            }
            vc = vsm1[seg][h1];
        }

        for (int step = 0; step < UNF; ++step) {
            float nv = 0.f;
            if (seg < RMAX) {
                float accN = ainN + s1s.x;
                float accD = ainD + s1s.y;
                #pragma unroll 4
                for (int i = 0; i < H1; ++i) {
                    float4 p = g_d1[i * H1 + h1];   // 64KB, L1-resident, reused 6x
                    float t = tanhfast(fmaf(p.x, vsm1[seg][i], p.y));
                    accN = fmaf(p.z, t, accN);
                    accD = fmaf(p.w, t, accD);
                }
                int row = min(row0 + seg, BK - 1);
                float n = noise1[(step * BK + row) * H1 + h1];
                float d = fmaf(-(hc.y + accD), vc, hc.x + accN) * hc.z;
                nv = fmaf(d, (1.0f / 6.0f), fmaf(hc.w, n, vc));
            }
            __syncthreads();
            if (seg < RMAX) { vsm1[seg][h1] = nv; vc = nv; }
            __syncthreads();
        }

        if (seg < RMAX) {
            int row = row0 + seg;
            if (row < BK) {
                out_particles[row * HS + H0 + h1] = vc;
                g_s1[row * H1 + h1] = vc;
            }
        }
    }

    // ---------- output (last CTA per b reduces) ----------
    __threadfence();
    __syncthreads();
    if (tid == 0) {
        sflag[0] = -1; sflag[1] = -1;
        int b0 = row0 >> 6, b1 = (row0 + R - 1) >> 6;
        int k = 0;
        for (int b = b0; b <= b1; ++b) {
            int cf = (b * K_) / RMAX;
            int cl = min(NCTA - 1, (b * K_ + 63) / RMAX);
            int tgt = cl - cf + 1;
            int old = atomicAdd(&g_cnt[b], 1);
            sflag[k++] = (old == tgt - 1) ? b : -1;
        }
    }
    __syncthreads();
    __threadfence();
    #pragma unroll
    for (int k = 0; k < 2; ++k) {
        int b = sflag[k];
        if (b >= 0 && tid < K_) {
            float acc = 0.f;
            #pragma unroll 8
            for (int kk = 0; kk < K_; ++kk)
                acc = fmaf(g_wts[b * K_ + kk], __ldcg(&g_s1[(b * K_ + kk) * H1 + tid]), acc);
            out[b * H1 + tid] = acc;
        }
    }
}

// ================= launch =================
extern "C" void kernel_launch(void* const* d_in, const int* in_sizes, int n_in,
                              void* d_out, int out_size)
{
    const float* x           = (const float*)d_in[0];
    const float* particles   = (const float*)d_in[1];
    const float* log_weights = (const float*)d_in[2];
    const float* noise0      = (const float*)d_in[3];
    const float* noise1      = (const float*)d_in[4];

    const int total = H0*H0 + H1*H1 + H0*H1 + H0 + H1 + H0 + H1 + H1
                    + B_*H0 + B_ + BK + B_;
    precompute_kernel<<<(total + 255) / 256, 256>>>(
        x, log_weights,
        (const float*)d_in[5],  (const float*)d_in[6],  (const float*)d_in[7],
        (const float*)d_in[8],  (const float*)d_in[9],  (const float*)d_in[10],
        (const float*)d_in[11],
        (const float*)d_in[12], (const float*)d_in[13], (const float*)d_in[14],
        (const float*)d_in[15], (const float*)d_in[16],
        (const float*)d_in[17], (const float*)d_in[18], (const float*)d_in[19],
        (const float*)d_in[20], (const float*)d_in[21], (const float*)d_in[22],
        (const float*)d_in[23],
        (const float*)d_in[24], (const float*)d_in[25], (const float*)d_in[26],
        (const float*)d_in[27], (const float*)d_in[28],
        (float*)d_out);

    float* out = (float*)d_out;
    main_kernel<<<NCTA, NTHR>>>(particles, noise0, noise1, out + B_ * H1, out);
}